// round 7
// baseline (speedup 1.0000x reference)
#include <cuda_runtime.h>
#include <cstdint>

// Problem constants (fixed by the reference)
#define NN      2048
#define DF      512
#define MSUP    512
#define TARGET  1536          // N - NUM_SUPER merges
#define MAXDEG  512
#define MAXE    (1 << 21)
#define INF64   0xFFFFFFFFFFFFFFFFULL

#define NBLK    148
#define NTH     1024
#define NALL    (NBLK * NTH)
#define NWARP   (NALL / 32)

// Output layout: X_coarse [512,512] | A_coarse [512,512] | P [2048,512]
#define XC_OFF  0
#define AC_OFF  262144
#define P_OFF   524288
#define OUT_N   1572864

// -------- scratch (device globals; no allocation allowed) --------
__device__ int                g_adj[NN * MAXDEG];   // 4 MB
__device__ int                g_deg[NN];
__device__ int                g_inter[NN * NN];     // 16 MB (upper triangle)
__device__ unsigned long long g_edges[MAXE];        // 16 MB
__device__ int                g_ne;
__device__ int                g_lab[NN];
__device__ unsigned long long g_mine[NN];
__device__ unsigned long long g_tlist[4096];
__device__ int                g_tn;
__device__ int                g_active;
__device__ int                g_rminfb[NN];
__device__ int                g_labels[NN];
__device__ float              g_wnode[NN];

// software grid barrier state (persists across replays; generation-based)
__device__ unsigned           g_barcnt = 0;
__device__ volatile unsigned  g_bargen = 0;

__device__ __forceinline__ void gridbar() {
    __threadfence();
    __syncthreads();
    if (threadIdx.x == 0) {
        unsigned gen = g_bargen;
        if (atomicAdd(&g_barcnt, 1u) == NBLK - 1) {
            g_barcnt = 0;
            __threadfence();
            g_bargen = gen + 1;
        } else {
            while (g_bargen == gen) __nanosleep(32);
        }
    }
    __syncthreads();
    __threadfence();
}

// -------- shared-memory overlay --------
// edges phase : sdeg[2048] int | sbuf[2048] u64 | sred[1024] u64  = 32768 B
// sweep phase : slab[2048] int                                   =  8192 B
// hook  phase : slab[2048] int | snew[2048] int                  = 16384 B
// finish phase: tl[2048] u64 | lab2[2048] int | mlist/ssz/swc[512]= 30720 B
// epilogue    : slabels[2048] int | swn[2048] float              = 16384 B

__device__ __forceinline__ void do_hook(char* smraw, int tid) {
    int* slab = (int*)smraw;
    int* snew = (int*)(smraw + 8192);
    __shared__ int s_h;
    for (int t = tid; t < NN; t += NTH) { slab[t] = g_lab[t]; snew[t] = -1; }
    if (tid == 0) s_h = 0;
    __syncthreads();
    for (int r = tid; r < NN; r += NTH) {
        if (slab[r] == r) {
            unsigned long long w = g_mine[r];
            if (w != INF64) {
                unsigned idx = (unsigned)(w & 0x3FFFFFu);
                int u = idx >> 11, v = idx & (NN - 1);
                int ru = slab[u], rv = slab[v];
                int o = (ru == r) ? rv : ru;
                bool mutual = (g_mine[o] == w);     // distinct weights
                if (!mutual || r > o) { snew[r] = o; atomicAdd(&s_h, 1); }
                if (!mutual || r < o) {             // append tree edge once
                    int p = atomicAdd(&g_tn, 1);
                    if (p < 4096) g_tlist[p] = w;
                }
            }
        }
    }
    __syncthreads();
    for (int r = tid; r < NN; r += NTH) {
        if (snew[r] >= 0) slab[r] = snew[r];
        g_mine[r] = INF64;
    }
    __syncthreads();
    for (int it = 0; it < 11; it++) {
        for (int t = tid; t < NN; t += NTH) snew[t] = slab[slab[t]];
        __syncthreads();
        for (int t = tid; t < NN; t += NTH) slab[t] = snew[t];
        __syncthreads();
    }
    for (int t = tid; t < NN; t += NTH) g_lab[t] = slab[t];
    if (tid == 0) g_active = s_h;
}

__device__ __forceinline__ int ser_find(int* p, int x) {
    while (p[x] != x) { p[x] = p[p[x]]; x = p[x]; }
    return x;
}

__device__ __forceinline__ void do_finish(char* smraw, int tid) {
    unsigned long long* tl = (unsigned long long*)smraw;          // 16384
    int*   lab2  = (int*)(smraw + 16384);                         //  8192
    int*   mlist = (int*)(smraw + 24576);                         //  2048
    int*   ssz   = (int*)(smraw + 26624);                         //  2048
    float* swc   = (float*)(smraw + 28672);                       //  2048
    __shared__ int s_cnt;
    int T = min(g_tn, 2047);

    for (int t = tid; t < 2048; t += NTH) tl[t] = (t < T) ? g_tlist[t] : INF64;
    for (int t = tid; t < NN; t += NTH) lab2[t] = t;
    for (int t = tid; t < MSUP; t += NTH) { ssz[t] = 0; mlist[t] = 0x7FFFFFFF; }
    if (tid == 0) s_cnt = 0;
    __syncthreads();

    // bitonic sort 2048 tree edges ascending by weight
    for (int k = 2; k <= 2048; k <<= 1)
        for (int j = k >> 1; j > 0; j >>= 1) {
            for (int t = tid; t < 2048; t += NTH) {
                int x = t ^ j;
                if (x > t) {
                    unsigned long long a = tl[t], b = tl[x];
                    if (((t & k) == 0) ? (a > b) : (a < b)) { tl[t] = b; tl[x] = a; }
                }
            }
            __syncthreads();
        }

    if (T >= TARGET) {
        // partition = CC of the first TARGET Kruskal-accepted edges
        for (int round = 0; round < 22; round++) {
            for (int e = tid; e < TARGET; e += NTH) {
                unsigned idx = (unsigned)(tl[e] & 0x3FFFFFu);
                int u = idx >> 11, v = idx & (NN - 1);
                int a = lab2[u], b = lab2[v];
                int m = min(a, b);
                if (a != m) atomicMin(&lab2[u], m);
                if (b != m) atomicMin(&lab2[v], m);
            }
            __syncthreads();
            for (int t = tid; t < NN; t += NTH) lab2[t] = lab2[lab2[t]];
            __syncthreads();
        }
    } else {
        // fallback (never expected): serial Kruskal tail incl. zero-jaccard pairs
        if (tid == 0) {
            int merged = 0;
            for (int e = 0; e < T && merged < TARGET; e++) {
                unsigned idx = (unsigned)(tl[e] & 0x3FFFFFu);
                int u = idx >> 11, v = idx & (NN - 1);
                int ru = ser_find(lab2, u), rv = ser_find(lab2, v);
                if (ru != rv) { lab2[rv] = ru; merged++; }
            }
            for (int i = 0; i < NN - 1 && merged < TARGET; i++)
                for (int j = i + 1; j < NN && merged < TARGET; j++)
                    if (g_inter[i * NN + j] == 0) {
                        int ri = ser_find(lab2, i), rj = ser_find(lab2, j);
                        if (ri != rj) { lab2[rj] = ri; merged++; }
                    }
            for (int v = 0; v < NN; v++) g_rminfb[v] = NN;
            for (int v = 0; v < NN; v++) {
                int r = ser_find(lab2, v);
                if (v < g_rminfb[r]) g_rminfb[r] = v;
            }
            for (int v = 0; v < NN; v++) g_labels[v] = g_rminfb[ser_find(lab2, v)];
        }
        __syncthreads();
        for (int t = tid; t < NN; t += NTH) lab2[t] = g_labels[t];
        __syncthreads();
    }

    // component minima -> sorted -> rank == first-occurrence label
    for (int v = tid; v < NN; v += NTH)
        if (lab2[v] == v) mlist[atomicAdd(&s_cnt, 1)] = v;
    __syncthreads();
    for (int k = 2; k <= MSUP; k <<= 1)
        for (int j = k >> 1; j > 0; j >>= 1) {
            for (int t = tid; t < MSUP; t += NTH) {
                int x = t ^ j;
                if (x > t) {
                    int a = mlist[t], b = mlist[x];
                    if (((t & k) == 0) ? (a > b) : (a < b)) { mlist[t] = b; mlist[x] = a; }
                }
            }
            __syncthreads();
        }
    for (int v = tid; v < NN; v += NTH) {
        int m = lab2[v];
        int lo = 0, hi = MSUP - 1;
        while (lo < hi) { int mid = (lo + hi) >> 1; if (mlist[mid] < m) lo = mid + 1; else hi = mid; }
        g_labels[v] = lo;
        atomicAdd(&ssz[lo], 1);
    }
    __syncthreads();
    for (int t = tid; t < MSUP; t += NTH)
        swc[t] = 1.0f / sqrtf((float)ssz[t] + 1e-10f);
    __syncthreads();
    for (int v = tid; v < NN; v += NTH)
        g_wnode[v] = swc[g_labels[v]];
}

// ==================== the one persistent kernel ====================
__global__ __launch_bounds__(NTH, 1)
void k_super(const float* __restrict__ X, const float* __restrict__ A,
             float* __restrict__ out) {
    __shared__ __align__(16) char smraw[32768];
    __shared__ int s_scnt, s_sbase;
    int tid = threadIdx.x, bid = blockIdx.x;
    int gtid = bid * NTH + tid;
    int lane = tid & 31;
    int gw = gtid >> 5;

    // ---- phase 0: init/zero ----
    {
        int4 z4 = make_int4(0, 0, 0, 0);
        float4 f4 = make_float4(0.f, 0.f, 0.f, 0.f);
        for (int i = gtid; i < NN * NN / 4; i += NALL)
            reinterpret_cast<int4*>(g_inter)[i] = z4;
        for (int i = gtid; i < OUT_N / 4; i += NALL)
            reinterpret_cast<float4*>(out)[i] = f4;
        for (int i = gtid; i < NN; i += NALL) { g_lab[i] = i; g_mine[i] = INF64; }
        if (gtid == 0) { g_ne = 0; g_tn = 0; g_active = 1; }
    }
    gridbar();

    // ---- phase 1: adjacency lists + degrees (warp per row) ----
    for (int row = gw; row < NN; row += NWARP) {
        const float* rowp = A + (size_t)row * NN;
        int cnt = 0;
        for (int k = 0; k < NN; k += 32) {
            float v = rowp[k + lane];
            unsigned b = __ballot_sync(0xFFFFFFFFu, v > 0.0f);
            if (v > 0.0f) {
                int pos = cnt + __popc(b & ((1u << lane) - 1u));
                if (pos < MAXDEG) g_adj[row * MAXDEG + pos] = k + lane;
            }
            cnt += __popc(b);
        }
        if (lane == 0) g_deg[row] = cnt;
    }
    gridbar();

    // ---- phase 2: sparse triangle counting ----
    for (int node = gw; node < NN; node += NWARP) {
        int d = min(g_deg[node], MAXDEG);
        const int* nb = &g_adj[node * MAXDEG];
        for (int a = 0; a < d - 1; a++) {
            int i = nb[a];
            int* irow = &g_inter[i * NN];
            for (int b = a + 1 + lane; b < d; b += 32)
                atomicAdd(&irow[nb[b]], 1);
        }
    }
    gridbar();

    // ---- phase 3: edge extraction + fused Boruvka sweep #1 ----
    {
        int* sdeg = (int*)smraw;
        unsigned long long* sbuf = (unsigned long long*)(smraw + 8192);
        unsigned long long* sred = (unsigned long long*)(smraw + 8192 + 16384);
        for (int t = tid; t < NN; t += NTH) sdeg[t] = g_deg[t];
        __syncthreads();
        for (int row = bid; row < NN - 1; row += NBLK) {
            if (tid == 0) s_scnt = 0;
            __syncthreads();
            int di = sdeg[row];
            const int* irow = &g_inter[row * NN];
            unsigned long long wmin = INF64;
            for (int j = row + 1 + tid; j < NN; j += NTH) {
                int inter = irow[j];
                if (inter > 0) {
                    int uni = di + sdeg[j] - inter;   // > 0 when inter > 0
                    float jac = __fdiv_rn((float)inter, (float)uni);
                    unsigned fb = __float_as_uint(jac);
                    unsigned long long w =
                        ((unsigned long long)(~fb) << 22) | (unsigned)(row * NN + j);
                    int p = atomicAdd(&s_scnt, 1);
                    sbuf[p] = w;
                    wmin = min(wmin, w);
                    atomicMin(&g_mine[j], w);         // sweep #1, v-side
                }
            }
            sred[tid] = wmin;
            __syncthreads();
            for (int d = 512; d > 0; d >>= 1) {
                if (tid < d) sred[tid] = min(sred[tid], sred[tid + d]);
                __syncthreads();
            }
            if (tid == 0) {
                if (sred[0] != INF64) atomicMin(&g_mine[row], sred[0]);
                s_sbase = atomicAdd(&g_ne, s_scnt);   // one global atomic per row
            }
            __syncthreads();
            for (int t = tid; t < s_scnt; t += NTH)
                if (s_sbase + t < MAXE) g_edges[s_sbase + t] = sbuf[t];
            __syncthreads();
        }
    }
    gridbar();

    // ---- phase 4: Boruvka (hook #1 already has sweep data) ----
    if (bid == 0) do_hook(smraw, tid);
    gridbar();
    for (int r = 0; r < 10; r++) {
        if (g_active == 0) break;     // uniform: read after barrier
        int* slab = (int*)smraw;
        for (int t = tid; t < NN; t += NTH) slab[t] = g_lab[t];
        __syncthreads();
        int ne = min(g_ne, MAXE);
        for (int e = gtid; e < ne; e += NALL) {
            unsigned long long w = g_edges[e];
            unsigned idx = (unsigned)(w & 0x3FFFFFu);
            int u = idx >> 11, v = idx & (NN - 1);
            int ru = slab[u], rv = slab[v];
            if (ru != rv) {
                atomicMin(&g_mine[ru], w);
                atomicMin(&g_mine[rv], w);
            }
        }
        gridbar();
        if (bid == 0) do_hook(smraw, tid);
        gridbar();
    }

    // ---- phase 5: finish (block 0) ----
    if (bid == 0) do_finish(smraw, tid);
    gridbar();

    // ---- phase 6: epilogue ----
    {
        int*   slabels = (int*)smraw;
        float* swn     = (float*)(smraw + 8192);
        for (int t = tid; t < NN; t += NTH) {
            slabels[t] = g_labels[t];
            swn[t] = g_wnode[t];
        }
        __syncthreads();
        // P
        for (int i = gtid; i < NN; i += NALL)
            out[P_OFF + i * MSUP + slabels[i]] = swn[i];
        // X_coarse = P^T X
        for (int t = gtid; t < NN * DF; t += NALL) {
            int i = t >> 9, d = t & (DF - 1);
            atomicAdd(&out[XC_OFF + slabels[i] * DF + d], swn[i] * X[t]);
        }
        // A_coarse = P^T A P over adjacency lists
        for (int node = gw; node < NN; node += NWARP) {
            int d = min(g_deg[node], MAXDEG);
            float wi = swn[node];
            int li = slabels[node];
            for (int a = lane; a < d; a += 32) {
                int j = g_adj[node * MAXDEG + a];
                float v = A[(size_t)node * NN + j];
                atomicAdd(&out[AC_OFF + li * MSUP + slabels[j]], wi * swn[j] * v);
            }
        }
    }
}

// -------- launch --------
extern "C" void kernel_launch(void* const* d_in, const int* in_sizes, int n_in,
                              void* d_out, int out_size) {
    const float* X = (const float*)d_in[0];
    const float* A = (const float*)d_in[1];
    float* out = (float*)d_out;
    k_super<<<NBLK, NTH>>>(X, A, out);
}